// round 15
// baseline (speedup 1.0000x reference)
#include <cuda_runtime.h>
#include <cuda_bf16.h>
#include <cstdint>

#define BATCH 96
#define SEQ   320
#define DIM   256
#define HEADS 8
#define DHEAD 32
#define NROWS (BATCH*SEQ)   /* 30720 */
#define NQKV  768
#define CTXLD (HEADS*SEQ)   /* 2560 */

// ---------------- scratch (device globals: no allocation allowed) ----------
__device__ __nv_bfloat16 g_a_hi[NROWS*DIM], g_a_lo[NROWS*DIM];   // LN out split
__device__ __nv_bfloat16 g_wt_hi[NQKV*DIM], g_wt_lo[NQKV*DIM];   // W^T [n][k]
__device__ __nv_bfloat16 g_q_hi[NROWS*DIM], g_q_lo[NROWS*DIM];
__device__ __nv_bfloat16 g_k_hi[NROWS*DIM], g_k_lo[NROWS*DIM];
__device__ __nv_bfloat16 g_v_hi[NROWS*DIM], g_v_lo[NROWS*DIM];
__device__ float g_o[NROWS*DIM];

// ---------------- helpers ----------------------------------------------------
__device__ __forceinline__ uint32_t smem_u32(const void* p) {
    uint32_t a;
    asm("{ .reg .u64 t; cvta.to.shared.u64 t, %1; cvt.u32.u64 %0, t; }"
        : "=r"(a) : "l"(p));
    return a;
}

#define LDSM4(R, A)                                                           \
    asm volatile("ldmatrix.sync.aligned.m8n8.x4.shared.b16 {%0,%1,%2,%3}, [%4];" \
                 : "=r"((R)[0]), "=r"((R)[1]), "=r"((R)[2]), "=r"((R)[3])     \
                 : "r"(A))
#define LDSM4T(R, A)                                                          \
    asm volatile("ldmatrix.sync.aligned.m8n8.x4.trans.shared.b16 {%0,%1,%2,%3}, [%4];" \
                 : "=r"((R)[0]), "=r"((R)[1]), "=r"((R)[2]), "=r"((R)[3])     \
                 : "r"(A))
#define MMA16816(C, A, B)                                                     \
    asm volatile("mma.sync.aligned.m16n8k16.row.col.f32.bf16.bf16.f32 "       \
                 "{%0,%1,%2,%3},{%4,%5,%6,%7},{%8,%9},{%0,%1,%2,%3};"         \
                 : "+f"((C)[0]), "+f"((C)[1]), "+f"((C)[2]), "+f"((C)[3])     \
                 : "r"((A)[0]), "r"((A)[1]), "r"((A)[2]), "r"((A)[3]),        \
                   "r"((B)[0]), "r"((B)[1]))

#define CP16(dst, src)                                                        \
    asm volatile("cp.async.cg.shared.global [%0], [%1], 16;"                  \
                 :: "r"(dst), "l"(src) : "memory")
#define CP_COMMIT() asm volatile("cp.async.commit_group;" ::: "memory")
#define CP_WAIT1()  asm volatile("cp.async.wait_group 1;" ::: "memory")
#define CP_WAIT0()  asm volatile("cp.async.wait_group 0;" ::: "memory")

__device__ __forceinline__ void split_bf16(float v, __nv_bfloat16& h, __nv_bfloat16& l)
{
    h = __float2bfloat16(v);
    l = __float2bfloat16(v - __bfloat162float(h));
}
// pack two fp32 into {hi-bf16 pair, lo-bf16 pair} uint32 regs (x = low half)
__device__ __forceinline__ void pack_split2(float a, float b, uint32_t& hi, uint32_t& lo)
{
    __nv_bfloat162 H, L;
    split_bf16(a, H.x, L.x);
    split_bf16(b, H.y, L.y);
    hi = *(uint32_t*)&H;
    lo = *(uint32_t*)&L;
}

// xs row (Bi, n)  ->  offset into the 7D x tensor (elems = innermost size)
__device__ __forceinline__ size_t x_offset(int Bi, int n, int elems)
{
    int b  = Bi / 48, xy = Bi % 48;
    int gx = xy >> 3, gy = xy & 7;
    int l  = n >> 6,  r  = n & 63;
    int w1 = r >> 3,  w2 = r & 7;
    return ((((((size_t)b*5 + l)*6 + gx)*8 + gy)*8 + w1)*8 + w2) * (size_t)elems;
}

// ---------------- kernel 0: weight transpose + bf16 split -------------------
__global__ __launch_bounds__(256)
void wprep_kernel(const float* __restrict__ wq, const float* __restrict__ wkv)
{
    int idx = blockIdx.x * 256 + threadIdx.x;    // 0 .. 768*256-1
    int n = idx >> 8;
    int k = idx & 255;
    float w = (n < 256) ? wq[(size_t)k * 256 + n]
                        : wkv[(size_t)k * 512 + (n - 256)];
    __nv_bfloat16 h, l;
    split_bf16(w, h, l);
    g_wt_hi[idx] = h;
    g_wt_lo[idx] = l;
}

// ---------------- kernel 1: LayerNorm, warp-per-row (shuffle-only) ----------
__global__ __launch_bounds__(256)
void ln_kernel(const float* __restrict__ x,
               const float* __restrict__ gamma,
               const float* __restrict__ beta)
{
    int wid = threadIdx.x >> 5, lane = threadIdx.x & 31;
    int row = blockIdx.x * 8 + wid;       // 0..30719
    int Bi  = row / SEQ;
    int n   = row % SEQ;
    size_t xoff = x_offset(Bi, n, DIM);

    float v[8];
    #pragma unroll
    for (int j = 0; j < 8; j++)
        v[j] = x[xoff + lane + 32*j];

    float s1 = 0.f, s2 = 0.f;
    #pragma unroll
    for (int j = 0; j < 8; j++) { s1 += v[j]; s2 += v[j]*v[j]; }
    #pragma unroll
    for (int off = 16; off > 0; off >>= 1) {
        s1 += __shfl_xor_sync(0xffffffff, s1, off);
        s2 += __shfl_xor_sync(0xffffffff, s2, off);
    }
    float mu  = s1 * (1.0f / DIM);
    float var = s2 * (1.0f / DIM) - mu * mu;
    float rs  = rsqrtf(var + 1e-5f);

    #pragma unroll
    for (int j = 0; j < 8; j++) {
        int d = lane + 32*j;
        float y = (v[j] - mu) * rs * gamma[d] + beta[d];
        __nv_bfloat16 h, l;
        split_bf16(y, h, l);
        g_a_hi[(size_t)row * DIM + d] = h;
        g_a_lo[(size_t)row * DIM + d] = l;
    }
}

// ---------------- kernel 2: QKV projection (bf16 split, 3-stage cp.async) ---
// C(30720x768) = A(30720x256) @ W'(256x768); CTA tile 128x128, warp 32x64.
// 3-stage pipeline: each stage has TWO compute phases to land -> wait never
// blocks. One barrier per K-step. Dynamic smem 73728B.
#define QKV_STAGE 24576
#define QKV_SMEM  (3*QKV_STAGE)

__global__ __launch_bounds__(256)
void qkv_mma(void)
{
    extern __shared__ __align__(16) __nv_bfloat16 dsm[];
    uint32_t sb = smem_u32(dsm);
    // per stage: Ah @+0, Al @+6144, Bh @+12288, Bl @+18432 (each 128x24 bf16)

    int tid = threadIdx.x;
    int w = tid >> 5, lane = tid & 31;
    int bx = blockIdx.x;                  // 0..5 (N tile)
    int row0 = blockIdx.y * 128;
    int col0 = bx * 128;

    int wm = w >> 1;
    int wn = w & 1;

    int lr16 = lane & 15, lk16 = (lane >> 4) * 16;
    int l7 = lane & 7, lb3 = (lane >> 3) & 1, lb4 = lane >> 4;

    float c[2][8][4];
    #pragma unroll
    for (int i = 0; i < 2; i++)
        #pragma unroll
        for (int j = 0; j < 8; j++)
            #pragma unroll
            for (int q = 0; q < 4; q++) c[i][j][q] = 0.f;

    int r = tid >> 1, hf = tid & 1;
    size_t gA = (size_t)(row0 + r) * 256 + hf * 8;
    size_t gB = (size_t)(col0 + r) * 256 + hf * 8;
    uint32_t sOfs = (uint32_t)(r * 48 + hf * 16);

    auto issue_stage = [&](int s) {
        uint32_t off = sb + (uint32_t)(s % 3) * QKV_STAGE + sOfs;
        size_t ko = (size_t)s * 16;
        CP16(off,          g_a_hi  + gA + ko);
        CP16(off +  6144,  g_a_lo  + gA + ko);
        CP16(off + 12288,  g_wt_hi + gB + ko);
        CP16(off + 18432,  g_wt_lo + gB + ko);
        CP_COMMIT();
    };

    // prologue: stages 0 and 1 in flight
    issue_stage(0);
    issue_stage(1);

    for (int ks = 0; ks < 16; ks++) {
        if (ks == 15) { CP_WAIT0(); } else { CP_WAIT1(); }
        __syncthreads();     // all threads past reads of buffer (ks+2)%3

        if (ks < 14) issue_stage(ks + 2);

        uint32_t base = sb + (uint32_t)(ks % 3) * QKV_STAGE;
        uint32_t aAh = base, aAl = base + 6144;
        uint32_t aBh = base + 12288, aBl = base + 18432;

        uint32_t ah[2][4], al[2][4], bb[8][2];
        #pragma unroll
        for (int mi = 0; mi < 2; mi++) {
            uint32_t ra = (uint32_t)((wm*32 + mi*16 + lr16) * 48 + lk16);
            LDSM4(ah[mi], aAh + ra);
            LDSM4(al[mi], aAl + ra);
        }
        // B-hi: x4-pair loads (two n-tiles per ldmatrix)
        #pragma unroll
        for (int pi = 0; pi < 4; pi++) {
            uint32_t ad = (uint32_t)((wn*64 + pi*16 + lb4*8 + l7) * 48 + lb3*16);
            uint32_t t[4];
            LDSM4(t, aBh + ad);
            bb[2*pi][0] = t[0]; bb[2*pi][1] = t[1];
            bb[2*pi+1][0] = t[2]; bb[2*pi+1][1] = t[3];
        }
        #pragma unroll
        for (int mi = 0; mi < 2; mi++)
            #pragma unroll
            for (int ni = 0; ni < 8; ni++) {
                MMA16816(c[mi][ni], ah[mi], bb[ni]);   // Ah*Bh
                MMA16816(c[mi][ni], al[mi], bb[ni]);   // Al*Bh
            }
        // B-lo: x4-pair loads
        #pragma unroll
        for (int pi = 0; pi < 4; pi++) {
            uint32_t ad = (uint32_t)((wn*64 + pi*16 + lb4*8 + l7) * 48 + lb3*16);
            uint32_t t[4];
            LDSM4(t, aBl + ad);
            bb[2*pi][0] = t[0]; bb[2*pi][1] = t[1];
            bb[2*pi+1][0] = t[2]; bb[2*pi+1][1] = t[3];
        }
        #pragma unroll
        for (int mi = 0; mi < 2; mi++)
            #pragma unroll
            for (int ni = 0; ni < 8; ni++)
                MMA16816(c[mi][ni], ah[mi], bb[ni]);   // Ah*Bl
    }

    // epilogue: split + store bf16 hi/lo into q/k/v
    __nv_bfloat16 *dh, *dl;
    int cbase;
    if (bx < 2)      { dh = g_q_hi; dl = g_q_lo; cbase = bx * 128; }
    else if (bx < 4) { dh = g_k_hi; dl = g_k_lo; cbase = (bx - 2) * 128; }
    else             { dh = g_v_hi; dl = g_v_lo; cbase = (bx - 4) * 128; }

    int g = lane >> 2, tg = lane & 3;
    #pragma unroll
    for (int mi = 0; mi < 2; mi++) {
        #pragma unroll
        for (int ni = 0; ni < 8; ni++) {
            int cl = cbase + wn*64 + ni*8 + tg*2;
            #pragma unroll
            for (int half = 0; half < 2; half++) {
                int rowg = row0 + wm*32 + mi*16 + g + half*8;
                uint32_t H, L;
                pack_split2(c[mi][ni][half*2+0], c[mi][ni][half*2+1], H, L);
                *(uint32_t*)(dh + (size_t)rowg * 256 + cl) = H;
                *(uint32_t*)(dl + (size_t)rowg * 256 + cl) = L;
            }
        }
    }
}

// ---------------- kernel 3: attention (flash, warp-private softmax) ---------
// grid (5 n-tiles, 8 heads, 96 batch), 128 thr = 4 warps.
// Bias registers software-pipelined one chunk ahead: load for chunk i+1
// issues right after chunk i's bias-add (b regs dead there) -> 2.5-phase
// load-to-use window, zero extra registers. One barrier per chunk.
__global__ __launch_bounds__(128)
void attn_mma(const float* __restrict__ ctx)
{
    __shared__ __align__(16) __nv_bfloat16 sK[2][2][64][40];  // [stage][hi/lo]
    __shared__ __align__(16) __nv_bfloat16 sV[2][2][64][40];

    int tid = threadIdx.x;
    int lane = tid & 31, wm = tid >> 5;
    int g = lane >> 2, tg = lane & 3;
    int lr16 = lane & 15, lk16 = (lane >> 4) * 16;

    int nt = blockIdx.x, h = blockIdx.y, Bi = blockIdx.z;
    int n0 = nt * 64;
    size_t rowbase = (size_t)Bi * SEQ;

    uint32_t aK[2][2], aV[2][2];
    #pragma unroll
    for (int s = 0; s < 2; s++) {
        #pragma unroll
        for (int hl = 0; hl < 2; hl++) {
            aK[s][hl] = smem_u32(&sK[s][hl][0][0]);
            aV[s][hl] = smem_u32(&sV[s][hl][0][0]);
        }
    }

    // cp.async mapping: row = tid>>1, 32-byte half cb
    int cr = tid >> 1;
    int cb = (tid & 1) * 32;
    uint32_t so = (uint32_t)(cr * 80 + cb);
    int ce = cb >> 1;                    // element offset within row (bf16)

    // ldmatrix x4 lane addressing (K pairs / V-trans pairs)
    int l7 = lane & 7, lb3 = (lane >> 3) & 1, lb4 = lane >> 4;

    // ---- prologue: Q staged through stage-1 K region, then K/V stage 0 ----
    {
        size_t gq = (rowbase + n0 + cr) * 256 + h * 32 + ce;
        CP16(aK[1][0] + so,      g_q_hi + gq);
        CP16(aK[1][0] + so + 16, g_q_hi + gq + 8);
        CP16(aK[1][1] + so,      g_q_lo + gq);
        CP16(aK[1][1] + so + 16, g_q_lo + gq + 8);
        CP_COMMIT();
        size_t gb = (rowbase + 0 + cr) * 256 + h * 32 + ce;
        CP16(aK[0][0] + so,      g_k_hi + gb);
        CP16(aK[0][0] + so + 16, g_k_hi + gb + 8);
        CP16(aK[0][1] + so,      g_k_lo + gb);
        CP16(aK[0][1] + so + 16, g_k_lo + gb + 8);
        CP16(aV[0][0] + so,      g_v_hi + gb);
        CP16(aV[0][0] + so + 16, g_v_hi + gb + 8);
        CP16(aV[0][1] + so,      g_v_lo + gb);
        CP16(aV[0][1] + so + 16, g_v_lo + gb + 8);
        CP_COMMIT();
    }
    CP_WAIT1();              // Q group complete (stage-0 K/V may still fly)
    __syncthreads();

    uint32_t qh[2][4], ql[2][4];
    #pragma unroll
    for (int kk = 0; kk < 2; kk++) {
        uint32_t ra = (uint32_t)((wm*16 + lr16) * 80 + lk16 + kk*32);
        LDSM4(qh[kk], aK[1][0] + ra);
        LDSM4(ql[kk], aK[1][1] + ra);
    }

    const float* ctxb = ctx + (size_t)Bi * SEQ * CTXLD + (size_t)h * SEQ;

    float o[4][4];
    #pragma unroll
    for (int vi = 0; vi < 4; vi++)
        #pragma unroll
        for (int q = 0; q < 4; q++) o[vi][q] = 0.f;
    float m_lo = -1e30f, m_hi = -1e30f, l_lo = 0.f, l_hi = 0.f;

    int rl = wm*16 + g, rh = rl + 8;
    const float* bias_l = ctxb + (size_t)(n0 + rl) * CTXLD;
    const float* bias_h = ctxb + (size_t)(n0 + rh) * CTXLD;

    // ---- bias for chunk 0 loaded in prologue ----
    float b[8][4];
    #pragma unroll
    for (int ni = 0; ni < 8; ni++) {
        int colm = ni*8 + tg*2;
        float2 b0 = *(const float2*)(bias_l + colm);
        float2 b1 = *(const float2*)(bias_h + colm);
        b[ni][0] = b0.x; b[ni][1] = b0.y; b[ni][2] = b1.x; b[ni][3] = b1.y;
    }

    for (int it = 0; it < 5; it++) {
        int m0 = it * 64, stg = it & 1;

        CP_WAIT0();          // stage stg data (issued last iteration) ready
        __syncthreads();     // all warps past previous reads; data visible

        if (it < 4) {        // issue next stage into the buffer just freed
            size_t gb = (rowbase + m0 + 64 + cr) * 256 + h * 32 + ce;
            int ns = stg ^ 1;
            CP16(aK[ns][0] + so,      g_k_hi + gb);
            CP16(aK[ns][0] + so + 16, g_k_hi + gb + 8);
            CP16(aK[ns][1] + so,      g_k_lo + gb);
            CP16(aK[ns][1] + so + 16, g_k_lo + gb + 8);
            CP16(aV[ns][0] + so,      g_v_hi + gb);
            CP16(aV[ns][0] + so + 16, g_v_hi + gb + 8);
            CP16(aV[ns][1] + so,      g_v_lo + gb);
            CP16(aV[ns][1] + so + 16, g_v_lo + gb + 8);
            CP_COMMIT();
        }

        // ---- S = Q K^T (zero-init; independent of bias loads) ----
        float s[8][4];
        #pragma unroll
        for (int ni = 0; ni < 8; ni++)
            #pragma unroll
            for (int q = 0; q < 4; q++) s[ni][q] = 0.f;

        #pragma unroll
        for (int kk = 0; kk < 2; kk++) {
            uint32_t bh[8][2], bl[8][2];
            #pragma unroll
            for (int pi = 0; pi < 4; pi++) {
                uint32_t ad = (uint32_t)((pi*16 + lb4*8 + l7) * 80
                                         + kk*32 + lb3*16);
                uint32_t t[4];
                LDSM4(t, aK[stg][0] + ad);
                bh[2*pi][0] = t[0]; bh[2*pi][1] = t[1];
                bh[2*pi+1][0] = t[2]; bh[2*pi+1][1] = t[3];
                LDSM4(t, aK[stg][1] + ad);
                bl[2*pi][0] = t[0]; bl[2*pi][1] = t[1];
                bl[2*pi+1][0] = t[2]; bl[2*pi+1][1] = t[3];
            }
            #pragma unroll
            for (int ni = 0; ni < 8; ni++) {
                MMA16816(s[ni], qh[kk], bh[ni]);
                MMA16816(s[ni], ql[kk], bh[ni]);
                MMA16816(s[ni], qh[kk], bl[ni]);
            }
        }

        // ---- add bias (loaded one full chunk ago) ----
        #pragma unroll
        for (int ni = 0; ni < 8; ni++) {
            s[ni][0] += b[ni][0]; s[ni][1] += b[ni][1];
            s[ni][2] += b[ni][2]; s[ni][3] += b[ni][3];
        }

        // ---- refill b for NEXT chunk (b is dead here; 2.5-phase window) ----
        if (it < 4) {
            #pragma unroll
            for (int ni = 0; ni < 8; ni++) {
                int colm = m0 + 64 + ni*8 + tg*2;
                float2 b0 = *(const float2*)(bias_l + colm);
                float2 b1 = *(const float2*)(bias_h + colm);
                b[ni][0] = b0.x; b[ni][1] = b0.y;
                b[ni][2] = b1.x; b[ni][3] = b1.y;
            }
        }

        // ---- warp-private online softmax (rows rl, rh) ----
        float mx0 = s[0][0], mx1 = s[0][2];
        #pragma unroll
        for (int ni = 0; ni < 8; ni++) {
            mx0 = fmaxf(mx0, fmaxf(s[ni][0], s[ni][1]));
            mx1 = fmaxf(mx1, fmaxf(s[ni][2], s[ni][3]));
        }
        mx0 = fmaxf(mx0, __shfl_xor_sync(0xffffffff, mx0, 1));
        mx0 = fmaxf(mx0, __shfl_xor_sync(0xffffffff, mx0, 2));
        mx1 = fmaxf(mx1, __shfl_xor_sync(0xffffffff, mx1, 1));
        mx1 = fmaxf(mx1, __shfl_xor_sync(0xffffffff, mx1, 2));

        float mn0 = fmaxf(m_lo, mx0);
        float mn1 = fmaxf(m_hi, mx1);
        float cor0 = __expf(m_lo - mn0);
        float cor1 = __expf(m_hi - mn1);
        m_lo = mn0; m_hi = mn1;

        float su0 = 0.f, su1 = 0.f;
        #pragma unroll
        for (int ni = 0; ni < 8; ni++) {
            s[ni][0] = __expf(s[ni][0] - mn0);
            s[ni][1] = __expf(s[ni][1] - mn0);
            s[ni][2] = __expf(s[ni][2] - mn1);
            s[ni][3] = __expf(s[ni][3] - mn1);
            su0 += s[ni][0] + s[ni][1];
            su1 += s[ni][2] + s[ni][3];
        }
        su0 += __shfl_xor_sync(0xffffffff, su0, 1);
        su0 += __shfl_xor_sync(0xffffffff, su0, 2);
        su1 += __shfl_xor_sync(0xffffffff, su1, 1);
        su1 += __shfl_xor_sync(0xffffffff, su1, 2);
        l_lo = l_lo * cor0 + su0;
        l_hi = l_hi * cor1 + su1;

        #pragma unroll
        for (int vi = 0; vi < 4; vi++) {
            o[vi][0] *= cor0; o[vi][1] *= cor0;
            o[vi][2] *= cor1; o[vi][3] *= cor1;
        }

        // ---- O += P @ V : P C-frags ARE A-frags; x4-pair trans V loads ----
        #pragma unroll
        for (int kk = 0; kk < 4; kk++) {
            uint32_t ph[4], pl[4];
            pack_split2(s[2*kk][0],   s[2*kk][1],   ph[0], pl[0]);
            pack_split2(s[2*kk][2],   s[2*kk][3],   ph[1], pl[1]);
            pack_split2(s[2*kk+1][0], s[2*kk+1][1], ph[2], pl[2]);
            pack_split2(s[2*kk+1][2], s[2*kk+1][3], ph[3], pl[3]);
            #pragma unroll
            for (int vp = 0; vp < 2; vp++) {
                uint32_t ad = (uint32_t)((kk*16 + lb3*8 + l7) * 80
                                         + (vp*2 + lb4) * 16);
                uint32_t th[4], tl[4];
                LDSM4T(th, aV[stg][0] + ad);
                LDSM4T(tl, aV[stg][1] + ad);
                uint32_t vh0[2] = {th[0], th[1]}, vh1[2] = {th[2], th[3]};
                uint32_t vl0[2] = {tl[0], tl[1]}, vl1[2] = {tl[2], tl[3]};
                MMA16816(o[vp*2],   ph, vh0);
                MMA16816(o[vp*2],   pl, vh0);
                MMA16816(o[vp*2],   ph, vl0);
                MMA16816(o[vp*2+1], ph, vh1);
                MMA16816(o[vp*2+1], pl, vh1);
                MMA16816(o[vp*2+1], ph, vl1);
            }
        }
    }

    // ---- normalize + store (no cross-warp reduction needed) ----
    float inv0 = 1.f / l_lo, inv1 = 1.f / l_hi;
    #pragma unroll
    for (int vi = 0; vi < 4; vi++) {
        int col = h*32 + vi*8 + tg*2;
        *(float2*)(g_o + (rowbase + n0 + rl) * 256 + col) =
            make_float2(o[vi][0] * inv0, o[vi][1] * inv0);
        *(float2*)(g_o + (rowbase + n0 + rh) * 256 + col) =
            make_float2(o[vi][2] * inv1, o[vi][3] * inv1);
    }
}

// ---------------- kernel 4: output projection + scatter ---------------------
__global__ __launch_bounds__(128)
void outproj_kernel(const float* __restrict__ wout, float* __restrict__ out)
{
    __shared__ __align__(16) float ws[DIM * DHEAD];
    int tid = threadIdx.x;
    for (int i = tid * 4; i < DIM * DHEAD; i += 128 * 4)
        *(float4*)&ws[i] = *(const float4*)&wout[i];
    __syncthreads();

    int row = blockIdx.x * 128 + tid;
    const float* arow = g_o + (size_t)row * DIM;

    float acc[32];
    #pragma unroll
    for (int j = 0; j < 32; j++) acc[j] = 0.f;

    for (int k4 = 0; k4 < DIM; k4 += 4) {
        float4 a = *(const float4*)(arow + k4);
        float av[4] = {a.x, a.y, a.z, a.w};
        #pragma unroll
        for (int kk = 0; kk < 4; kk++) {
            #pragma unroll
            for (int j4 = 0; j4 < 8; j4++) {
                float4 wv = *(const float4*)&ws[(k4 + kk) * DHEAD + j4 * 4];
                acc[j4*4+0] = fmaf(av[kk], wv.x, acc[j4*4+0]);
                acc[j4*4+1] = fmaf(av[kk], wv.y, acc[j4*4+1]);
                acc[j4*4+2] = fmaf(av[kk], wv.z, acc[j4*4+2]);
                acc[j4*4+3] = fmaf(av[kk], wv.w, acc[j4*4+3]);
            }
        }
    }

    int Bi = row / SEQ, n = row % SEQ;
    size_t off = x_offset(Bi, n, DHEAD);
    #pragma unroll
    for (int j4 = 0; j4 < 8; j4++)
        *(float4*)(out + off + j4 * 4) =
            make_float4(acc[j4*4], acc[j4*4+1], acc[j4*4+2], acc[j4*4+3]);
}

// ---------------- launch ----------------------------------------------------
extern "C" void kernel_launch(void* const* d_in, const int* in_sizes, int n_in,
                              void* d_out, int out_size)
{
    (void)out_size;
    // expected order: x, context, w_q, w_kv, w_out, ln_g, ln_b
    int ix = 0, ictx = 1, iwq = 2, iwkv = 3, iwout = 4, ig = 5, ib = 6;
    int g_seen = -1;
    for (int i = 0; i < n_in; i++) {
        switch (in_sizes[i]) {
            case 7864320:  ix = i;    break;
            case 78643200: ictx = i;  break;
            case 65536:    iwq = i;   break;
            case 131072:   iwkv = i;  break;
            case 8192:     iwout = i; break;
            case 256:
                if (g_seen < 0) { ig = i; g_seen = i; } else { ib = i; }
                break;
            default: break;
        }
    }

    const float* x    = (const float*)d_in[ix];
    const float* ctx  = (const float*)d_in[ictx];
    const float* wq   = (const float*)d_in[iwq];
    const float* wkv  = (const float*)d_in[iwkv];
    const float* wout = (const float*)d_in[iwout];
    const float* lng  = (const float*)d_in[ig];
    const float* lnb  = (const float*)d_in[ib];
    float* out = (float*)d_out;

    cudaFuncSetAttribute(qkv_mma, cudaFuncAttributeMaxDynamicSharedMemorySize,
                         QKV_SMEM);

    wprep_kernel<<<NQKV, 256>>>(wq, wkv);
    ln_kernel<<<NROWS/8, 256>>>(x, lng, lnb);

    dim3 g2(6, 240);
    qkv_mma<<<g2, 256, QKV_SMEM>>>();

    dim3 g3(5, HEADS, BATCH);
    attn_mma<<<g3, 128>>>(ctx);

    outproj_kernel<<<240, 128>>>(wout, out);
}

// round 16
// speedup vs baseline: 1.0241x; 1.0241x over previous
#include <cuda_runtime.h>
#include <cuda_bf16.h>
#include <cstdint>

#define BATCH 96
#define SEQ   320
#define DIM   256
#define HEADS 8
#define DHEAD 32
#define NROWS (BATCH*SEQ)   /* 30720 */
#define NQKV  768
#define CTXLD (HEADS*SEQ)   /* 2560 */

// ---------------- scratch (device globals: no allocation allowed) ----------
__device__ __nv_bfloat16 g_a_hi[NROWS*DIM], g_a_lo[NROWS*DIM];   // LN out split
__device__ __nv_bfloat16 g_wt_hi[NQKV*DIM], g_wt_lo[NQKV*DIM];   // W^T [n][k]
__device__ __nv_bfloat16 g_q_hi[NROWS*DIM], g_q_lo[NROWS*DIM];
__device__ __nv_bfloat16 g_k_hi[NROWS*DIM], g_k_lo[NROWS*DIM];
__device__ __nv_bfloat16 g_v_hi[NROWS*DIM], g_v_lo[NROWS*DIM];
__device__ float g_o[NROWS*DIM];

// ---------------- helpers ----------------------------------------------------
__device__ __forceinline__ uint32_t smem_u32(const void* p) {
    uint32_t a;
    asm("{ .reg .u64 t; cvta.to.shared.u64 t, %1; cvt.u32.u64 %0, t; }"
        : "=r"(a) : "l"(p));
    return a;
}

#define LDSM4(R, A)                                                           \
    asm volatile("ldmatrix.sync.aligned.m8n8.x4.shared.b16 {%0,%1,%2,%3}, [%4];" \
                 : "=r"((R)[0]), "=r"((R)[1]), "=r"((R)[2]), "=r"((R)[3])     \
                 : "r"(A))
#define LDSM4T(R, A)                                                          \
    asm volatile("ldmatrix.sync.aligned.m8n8.x4.trans.shared.b16 {%0,%1,%2,%3}, [%4];" \
                 : "=r"((R)[0]), "=r"((R)[1]), "=r"((R)[2]), "=r"((R)[3])     \
                 : "r"(A))
#define MMA16816(C, A, B)                                                     \
    asm volatile("mma.sync.aligned.m16n8k16.row.col.f32.bf16.bf16.f32 "       \
                 "{%0,%1,%2,%3},{%4,%5,%6,%7},{%8,%9},{%0,%1,%2,%3};"         \
                 : "+f"((C)[0]), "+f"((C)[1]), "+f"((C)[2]), "+f"((C)[3])     \
                 : "r"((A)[0]), "r"((A)[1]), "r"((A)[2]), "r"((A)[3]),        \
                   "r"((B)[0]), "r"((B)[1]))

#define CP16(dst, src)                                                        \
    asm volatile("cp.async.cg.shared.global [%0], [%1], 16;"                  \
                 :: "r"(dst), "l"(src) : "memory")
#define CP_COMMIT() asm volatile("cp.async.commit_group;" ::: "memory")
#define CP_WAIT1()  asm volatile("cp.async.wait_group 1;" ::: "memory")
#define CP_WAIT0()  asm volatile("cp.async.wait_group 0;" ::: "memory")

__device__ __forceinline__ void split_bf16(float v, __nv_bfloat16& h, __nv_bfloat16& l)
{
    h = __float2bfloat16(v);
    l = __float2bfloat16(v - __bfloat162float(h));
}
// pack two fp32 into {hi-bf16 pair, lo-bf16 pair} uint32 regs (x = low half)
__device__ __forceinline__ void pack_split2(float a, float b, uint32_t& hi, uint32_t& lo)
{
    __nv_bfloat162 H, L;
    split_bf16(a, H.x, L.x);
    split_bf16(b, H.y, L.y);
    hi = *(uint32_t*)&H;
    lo = *(uint32_t*)&L;
}

// xs row (Bi, n)  ->  offset into the 7D x tensor (elems = innermost size)
__device__ __forceinline__ size_t x_offset(int Bi, int n, int elems)
{
    int b  = Bi / 48, xy = Bi % 48;
    int gx = xy >> 3, gy = xy & 7;
    int l  = n >> 6,  r  = n & 63;
    int w1 = r >> 3,  w2 = r & 7;
    return ((((((size_t)b*5 + l)*6 + gx)*8 + gy)*8 + w1)*8 + w2) * (size_t)elems;
}

// ---------------- kernel 0: weight transpose + bf16 split -------------------
__global__ __launch_bounds__(256)
void wprep_kernel(const float* __restrict__ wq, const float* __restrict__ wkv)
{
    int idx = blockIdx.x * 256 + threadIdx.x;    // 0 .. 768*256-1
    int n = idx >> 8;
    int k = idx & 255;
    float w = (n < 256) ? wq[(size_t)k * 256 + n]
                        : wkv[(size_t)k * 512 + (n - 256)];
    __nv_bfloat16 h, l;
    split_bf16(w, h, l);
    g_wt_hi[idx] = h;
    g_wt_lo[idx] = l;
}

// ---------------- kernel 1: LayerNorm, warp-per-row (shuffle-only) ----------
__global__ __launch_bounds__(256)
void ln_kernel(const float* __restrict__ x,
               const float* __restrict__ gamma,
               const float* __restrict__ beta)
{
    int wid = threadIdx.x >> 5, lane = threadIdx.x & 31;
    int row = blockIdx.x * 8 + wid;       // 0..30719
    int Bi  = row / SEQ;
    int n   = row % SEQ;
    size_t xoff = x_offset(Bi, n, DIM);

    float v[8];
    #pragma unroll
    for (int j = 0; j < 8; j++)
        v[j] = x[xoff + lane + 32*j];

    float s1 = 0.f, s2 = 0.f;
    #pragma unroll
    for (int j = 0; j < 8; j++) { s1 += v[j]; s2 += v[j]*v[j]; }
    #pragma unroll
    for (int off = 16; off > 0; off >>= 1) {
        s1 += __shfl_xor_sync(0xffffffff, s1, off);
        s2 += __shfl_xor_sync(0xffffffff, s2, off);
    }
    float mu  = s1 * (1.0f / DIM);
    float var = s2 * (1.0f / DIM) - mu * mu;
    float rs  = rsqrtf(var + 1e-5f);

    #pragma unroll
    for (int j = 0; j < 8; j++) {
        int d = lane + 32*j;
        float y = (v[j] - mu) * rs * gamma[d] + beta[d];
        __nv_bfloat16 h, l;
        split_bf16(y, h, l);
        g_a_hi[(size_t)row * DIM + d] = h;
        g_a_lo[(size_t)row * DIM + d] = l;
    }
}

// ---------------- kernel 2: QKV projection (bf16 split, 2-stage cp.async) ---
// C(30720x768) = A(30720x256) @ W'(256x768); CTA tile 128x128, warp 32x64.
// ONE barrier per K-step; ALL 12 ldmatrix issued before the mma burst.
__global__ __launch_bounds__(256)
void qkv_mma(void)
{
    __shared__ __align__(16) __nv_bfloat16 sAh[2][128][24];   // 2-stage, 48B pitch
    __shared__ __align__(16) __nv_bfloat16 sAl[2][128][24];
    __shared__ __align__(16) __nv_bfloat16 sBh[2][128][24];
    __shared__ __align__(16) __nv_bfloat16 sBl[2][128][24];

    int tid = threadIdx.x;
    int w = tid >> 5, lane = tid & 31;
    int bx = blockIdx.x;                  // 0..5 (N tile)
    int row0 = blockIdx.y * 128;
    int col0 = bx * 128;

    int wm = w >> 1;
    int wn = w & 1;

    uint32_t aAh = smem_u32(&sAh[0][0][0]);
    uint32_t aAl = smem_u32(&sAl[0][0][0]);
    uint32_t aBh = smem_u32(&sBh[0][0][0]);
    uint32_t aBl = smem_u32(&sBl[0][0][0]);

    int lr16 = lane & 15, lk16 = (lane >> 4) * 16;
    int l7 = lane & 7, lb3 = (lane >> 3) & 1, lb4 = lane >> 4;

    float c[2][8][4];
    #pragma unroll
    for (int i = 0; i < 2; i++)
        #pragma unroll
        for (int j = 0; j < 8; j++)
            #pragma unroll
            for (int q = 0; q < 4; q++) c[i][j][q] = 0.f;

    int r = tid >> 1, hf = tid & 1;
    size_t gA = (size_t)(row0 + r) * 256 + hf * 8;
    size_t gB = (size_t)(col0 + r) * 256 + hf * 8;
    uint32_t sOfs = (uint32_t)(r * 48 + hf * 16);

    // prologue: stage 0
    CP16(aAh + sOfs, g_a_hi  + gA);
    CP16(aAl + sOfs, g_a_lo  + gA);
    CP16(aBh + sOfs, g_wt_hi + gB);
    CP16(aBl + sOfs, g_wt_lo + gB);
    CP_COMMIT();

    for (int ks = 0; ks < 16; ks++) {
        int stg = ks & 1;
        CP_WAIT0();          // data for stage stg ready (issued last iter)
        __syncthreads();     // everyone past previous stage's reads

        if (ks < 15) {       // next stage into buffer just freed
            int nst = stg ^ 1;
            uint32_t so = sOfs + (uint32_t)nst * 6144;
            size_t ko = (size_t)(ks + 1) * 16;
            CP16(aAh + so, g_a_hi  + gA + ko);
            CP16(aAl + so, g_a_lo  + gA + ko);
            CP16(aBh + so, g_wt_hi + gB + ko);
            CP16(aBl + so, g_wt_lo + gB + ko);
            CP_COMMIT();
        }

        uint32_t base = (uint32_t)stg * 6144;
        uint32_t ah[2][4], al[2][4], bbh[8][2], bbl[8][2];
        // ---- issue ALL 12 ldmatrix upfront (max LSU MLP, no mid-burst bubble)
        #pragma unroll
        for (int mi = 0; mi < 2; mi++) {
            uint32_t ra = base + (uint32_t)((wm*32 + mi*16 + lr16) * 48 + lk16);
            LDSM4(ah[mi], aAh + ra);
            LDSM4(al[mi], aAl + ra);
        }
        #pragma unroll
        for (int pi = 0; pi < 4; pi++) {
            uint32_t ad = base + (uint32_t)((wn*64 + pi*16 + lb4*8 + l7) * 48
                                            + lb3*16);
            uint32_t t[4];
            LDSM4(t, aBh + ad);
            bbh[2*pi][0] = t[0]; bbh[2*pi][1] = t[1];
            bbh[2*pi+1][0] = t[2]; bbh[2*pi+1][1] = t[3];
            uint32_t u[4];
            LDSM4(u, aBl + ad);
            bbl[2*pi][0] = u[0]; bbl[2*pi][1] = u[1];
            bbl[2*pi+1][0] = u[2]; bbl[2*pi+1][1] = u[3];
        }
        // ---- 48 mma burst ----
        #pragma unroll
        for (int mi = 0; mi < 2; mi++)
            #pragma unroll
            for (int ni = 0; ni < 8; ni++) {
                MMA16816(c[mi][ni], ah[mi], bbh[ni]);   // Ah*Bh
                MMA16816(c[mi][ni], al[mi], bbh[ni]);   // Al*Bh
                MMA16816(c[mi][ni], ah[mi], bbl[ni]);   // Ah*Bl
            }
    }

    // epilogue: split + store bf16 hi/lo into q/k/v
    __nv_bfloat16 *dh, *dl;
    int cbase;
    if (bx < 2)      { dh = g_q_hi; dl = g_q_lo; cbase = bx * 128; }
    else if (bx < 4) { dh = g_k_hi; dl = g_k_lo; cbase = (bx - 2) * 128; }
    else             { dh = g_v_hi; dl = g_v_lo; cbase = (bx - 4) * 128; }

    int g = lane >> 2, tg = lane & 3;
    #pragma unroll
    for (int mi = 0; mi < 2; mi++) {
        #pragma unroll
        for (int ni = 0; ni < 8; ni++) {
            int cl = cbase + wn*64 + ni*8 + tg*2;
            #pragma unroll
            for (int half = 0; half < 2; half++) {
                int rowg = row0 + wm*32 + mi*16 + g + half*8;
                uint32_t H, L;
                pack_split2(c[mi][ni][half*2+0], c[mi][ni][half*2+1], H, L);
                *(uint32_t*)(dh + (size_t)rowg * 256 + cl) = H;
                *(uint32_t*)(dl + (size_t)rowg * 256 + cl) = L;
            }
        }
    }
}

// ---------------- kernel 3: attention (flash, warp-private softmax) ---------
// grid (5 n-tiles, 8 heads, 96 batch), 128 thr = 4 warps.  (exact R14 version)
// Bias kept in separate registers; S zero-init -> bias consumed AFTER the QK
// phase (load-to-use window covers DRAM latency). One barrier per chunk.
__global__ __launch_bounds__(128)
void attn_mma(const float* __restrict__ ctx)
{
    __shared__ __align__(16) __nv_bfloat16 sK[2][2][64][40];  // [stage][hi/lo]
    __shared__ __align__(16) __nv_bfloat16 sV[2][2][64][40];

    int tid = threadIdx.x;
    int lane = tid & 31, wm = tid >> 5;
    int g = lane >> 2, tg = lane & 3;
    int lr16 = lane & 15, lk16 = (lane >> 4) * 16;

    int nt = blockIdx.x, h = blockIdx.y, Bi = blockIdx.z;
    int n0 = nt * 64;
    size_t rowbase = (size_t)Bi * SEQ;

    uint32_t aK[2][2], aV[2][2];
    #pragma unroll
    for (int s = 0; s < 2; s++) {
        #pragma unroll
        for (int hl = 0; hl < 2; hl++) {
            aK[s][hl] = smem_u32(&sK[s][hl][0][0]);
            aV[s][hl] = smem_u32(&sV[s][hl][0][0]);
        }
    }

    // cp.async mapping: row = tid>>1, 32-byte half cb
    int cr = tid >> 1;
    int cb = (tid & 1) * 32;
    uint32_t so = (uint32_t)(cr * 80 + cb);
    int ce = cb >> 1;                    // element offset within row (bf16)

    // ldmatrix x4 lane addressing (K pairs / V-trans pairs)
    int l7 = lane & 7, lb3 = (lane >> 3) & 1, lb4 = lane >> 4;

    // ---- prologue: Q staged through stage-1 K region, then K/V stage 0 ----
    {
        size_t gq = (rowbase + n0 + cr) * 256 + h * 32 + ce;
        CP16(aK[1][0] + so,      g_q_hi + gq);
        CP16(aK[1][0] + so + 16, g_q_hi + gq + 8);
        CP16(aK[1][1] + so,      g_q_lo + gq);
        CP16(aK[1][1] + so + 16, g_q_lo + gq + 8);
        CP_COMMIT();
        size_t gb = (rowbase + 0 + cr) * 256 + h * 32 + ce;
        CP16(aK[0][0] + so,      g_k_hi + gb);
        CP16(aK[0][0] + so + 16, g_k_hi + gb + 8);
        CP16(aK[0][1] + so,      g_k_lo + gb);
        CP16(aK[0][1] + so + 16, g_k_lo + gb + 8);
        CP16(aV[0][0] + so,      g_v_hi + gb);
        CP16(aV[0][0] + so + 16, g_v_hi + gb + 8);
        CP16(aV[0][1] + so,      g_v_lo + gb);
        CP16(aV[0][1] + so + 16, g_v_lo + gb + 8);
        CP_COMMIT();
    }
    CP_WAIT1();              // Q group complete (stage-0 K/V may still fly)
    __syncthreads();

    uint32_t qh[2][4], ql[2][4];
    #pragma unroll
    for (int kk = 0; kk < 2; kk++) {
        uint32_t ra = (uint32_t)((wm*16 + lr16) * 80 + lk16 + kk*32);
        LDSM4(qh[kk], aK[1][0] + ra);
        LDSM4(ql[kk], aK[1][1] + ra);
    }

    const float* ctxb = ctx + (size_t)Bi * SEQ * CTXLD + (size_t)h * SEQ;

    float o[4][4];
    #pragma unroll
    for (int vi = 0; vi < 4; vi++)
        #pragma unroll
        for (int q = 0; q < 4; q++) o[vi][q] = 0.f;
    float m_lo = -1e30f, m_hi = -1e30f, l_lo = 0.f, l_hi = 0.f;

    int rl = wm*16 + g, rh = rl + 8;
    const float* bias_l = ctxb + (size_t)(n0 + rl) * CTXLD;
    const float* bias_h = ctxb + (size_t)(n0 + rh) * CTXLD;

    for (int it = 0; it < 5; it++) {
        int m0 = it * 64, stg = it & 1;

        // ---- bias loads into SEPARATE regs; consumed only after QK ----
        float b[8][4];
        #pragma unroll
        for (int ni = 0; ni < 8; ni++) {
            int colm = m0 + ni*8 + tg*2;
            float2 b0 = *(const float2*)(bias_l + colm);
            float2 b1 = *(const float2*)(bias_h + colm);
            b[ni][0] = b0.x; b[ni][1] = b0.y; b[ni][2] = b1.x; b[ni][3] = b1.y;
        }

        CP_WAIT0();          // stage stg data (issued last iteration) ready
        __syncthreads();     // all warps past previous reads; data visible

        if (it < 4) {        // issue next stage into the buffer just freed
            size_t gb = (rowbase + m0 + 64 + cr) * 256 + h * 32 + ce;
            int ns = stg ^ 1;
            CP16(aK[ns][0] + so,      g_k_hi + gb);
            CP16(aK[ns][0] + so + 16, g_k_hi + gb + 8);
            CP16(aK[ns][1] + so,      g_k_lo + gb);
            CP16(aK[ns][1] + so + 16, g_k_lo + gb + 8);
            CP16(aV[ns][0] + so,      g_v_hi + gb);
            CP16(aV[ns][0] + so + 16, g_v_hi + gb + 8);
            CP16(aV[ns][1] + so,      g_v_lo + gb);
            CP16(aV[ns][1] + so + 16, g_v_lo + gb + 8);
            CP_COMMIT();
        }

        // ---- S = Q K^T (zero-init; no dependency on bias loads) ----
        float s[8][4];
        #pragma unroll
        for (int ni = 0; ni < 8; ni++)
            #pragma unroll
            for (int q = 0; q < 4; q++) s[ni][q] = 0.f;

        #pragma unroll
        for (int kk = 0; kk < 2; kk++) {
            uint32_t bh[8][2], bl[8][2];
            #pragma unroll
            for (int pi = 0; pi < 4; pi++) {
                uint32_t ad = (uint32_t)((pi*16 + lb4*8 + l7) * 80
                                         + kk*32 + lb3*16);
                uint32_t t[4];
                LDSM4(t, aK[stg][0] + ad);
                bh[2*pi][0] = t[0]; bh[2*pi][1] = t[1];
                bh[2*pi+1][0] = t[2]; bh[2*pi+1][1] = t[3];
                LDSM4(t, aK[stg][1] + ad);
                bl[2*pi][0] = t[0]; bl[2*pi][1] = t[1];
                bl[2*pi+1][0] = t[2]; bl[2*pi+1][1] = t[3];
            }
            #pragma unroll
            for (int ni = 0; ni < 8; ni++) {
                MMA16816(s[ni], qh[kk], bh[ni]);
                MMA16816(s[ni], ql[kk], bh[ni]);
                MMA16816(s[ni], qh[kk], bl[ni]);
            }
        }

        // ---- add bias (loads have had the whole QK phase to land) ----
        #pragma unroll
        for (int ni = 0; ni < 8; ni++) {
            s[ni][0] += b[ni][0]; s[ni][1] += b[ni][1];
            s[ni][2] += b[ni][2]; s[ni][3] += b[ni][3];
        }

        // ---- warp-private online softmax (rows rl, rh) ----
        float mx0 = s[0][0], mx1 = s[0][2];
        #pragma unroll
        for (int ni = 0; ni < 8; ni++) {
            mx0 = fmaxf(mx0, fmaxf(s[ni][0], s[ni][1]));
            mx1 = fmaxf(mx1, fmaxf(s[ni][2], s[ni][3]));
        }
        mx0 = fmaxf(mx0, __shfl_xor_sync(0xffffffff, mx0, 1));
        mx0 = fmaxf(mx0, __shfl_xor_sync(0xffffffff, mx0, 2));
        mx1 = fmaxf(mx1, __shfl_xor_sync(0xffffffff, mx1, 1));
        mx1 = fmaxf(mx1, __shfl_xor_sync(0xffffffff, mx1, 2));

        float mn0 = fmaxf(m_lo, mx0);
        float mn1 = fmaxf(m_hi, mx1);
        float cor0 = __expf(m_lo - mn0);
        float cor1 = __expf(m_hi - mn1);
        m_lo = mn0; m_hi = mn1;

        float su0 = 0.f, su1 = 0.f;
        #pragma unroll
        for (int ni = 0; ni < 8; ni++) {
            s[ni][0] = __expf(s[ni][0] - mn0);
            s[ni][1] = __expf(s[ni][1] - mn0);
            s[ni][2] = __expf(s[ni][2] - mn1);
            s[ni][3] = __expf(s[ni][3] - mn1);
            su0 += s[ni][0] + s[ni][1];
            su1 += s[ni][2] + s[ni][3];
        }
        su0 += __shfl_xor_sync(0xffffffff, su0, 1);
        su0 += __shfl_xor_sync(0xffffffff, su0, 2);
        su1 += __shfl_xor_sync(0xffffffff, su1, 1);
        su1 += __shfl_xor_sync(0xffffffff, su1, 2);
        l_lo = l_lo * cor0 + su0;
        l_hi = l_hi * cor1 + su1;

        #pragma unroll
        for (int vi = 0; vi < 4; vi++) {
            o[vi][0] *= cor0; o[vi][1] *= cor0;
            o[vi][2] *= cor1; o[vi][3] *= cor1;
        }

        // ---- O += P @ V : P C-frags ARE A-frags; x4-pair trans V loads ----
        #pragma unroll
        for (int kk = 0; kk < 4; kk++) {
            uint32_t ph[4], pl[4];
            pack_split2(s[2*kk][0],   s[2*kk][1],   ph[0], pl[0]);
            pack_split2(s[2*kk][2],   s[2*kk][3],   ph[1], pl[1]);
            pack_split2(s[2*kk+1][0], s[2*kk+1][1], ph[2], pl[2]);
            pack_split2(s[2*kk+1][2], s[2*kk+1][3], ph[3], pl[3]);
            #pragma unroll
            for (int vp = 0; vp < 2; vp++) {
                uint32_t ad = (uint32_t)((kk*16 + lb3*8 + l7) * 80
                                         + (vp*2 + lb4) * 16);
                uint32_t th[4], tl[4];
                LDSM4T(th, aV[stg][0] + ad);
                LDSM4T(tl, aV[stg][1] + ad);
                uint32_t vh0[2] = {th[0], th[1]}, vh1[2] = {th[2], th[3]};
                uint32_t vl0[2] = {tl[0], tl[1]}, vl1[2] = {tl[2], tl[3]};
                MMA16816(o[vp*2],   ph, vh0);
                MMA16816(o[vp*2],   pl, vh0);
                MMA16816(o[vp*2],   ph, vl0);
                MMA16816(o[vp*2+1], ph, vh1);
                MMA16816(o[vp*2+1], pl, vh1);
                MMA16816(o[vp*2+1], ph, vl1);
            }
        }
    }

    // ---- normalize + store (no cross-warp reduction needed) ----
    float inv0 = 1.f / l_lo, inv1 = 1.f / l_hi;
    #pragma unroll
    for (int vi = 0; vi < 4; vi++) {
        int col = h*32 + vi*8 + tg*2;
        *(float2*)(g_o + (rowbase + n0 + rl) * 256 + col) =
            make_float2(o[vi][0] * inv0, o[vi][1] * inv0);
        *(float2*)(g_o + (rowbase + n0 + rh) * 256 + col) =
            make_float2(o[vi][2] * inv1, o[vi][3] * inv1);
    }
}

// ---------------- kernel 4: output projection + scatter ---------------------
__global__ __launch_bounds__(128)
void outproj_kernel(const float* __restrict__ wout, float* __restrict__ out)
{
    __shared__ __align__(16) float ws[DIM * DHEAD];
    int tid = threadIdx.x;
    for (int i = tid * 4; i < DIM * DHEAD; i += 128 * 4)
        *(float4*)&ws[i] = *(const float4*)&wout[i];
    __syncthreads();

    int row = blockIdx.x * 128 + tid;
    const float* arow = g_o + (size_t)row * DIM;

    float acc[32];
    #pragma unroll
    for (int j = 0; j < 32; j++) acc[j] = 0.f;

    for (int k4 = 0; k4 < DIM; k4 += 4) {
        float4 a = *(const float4*)(arow + k4);
        float av[4] = {a.x, a.y, a.z, a.w};
        #pragma unroll
        for (int kk = 0; kk < 4; kk++) {
            #pragma unroll
            for (int j4 = 0; j4 < 8; j4++) {
                float4 wv = *(const float4*)&ws[(k4 + kk) * DHEAD + j4 * 4];
                acc[j4*4+0] = fmaf(av[kk], wv.x, acc[j4*4+0]);
                acc[j4*4+1] = fmaf(av[kk], wv.y, acc[j4*4+1]);
                acc[j4*4+2] = fmaf(av[kk], wv.z, acc[j4*4+2]);
                acc[j4*4+3] = fmaf(av[kk], wv.w, acc[j4*4+3]);
            }
        }
    }

    int Bi = row / SEQ, n = row % SEQ;
    size_t off = x_offset(Bi, n, DHEAD);
    #pragma unroll
    for (int j4 = 0; j4 < 8; j4++)
        *(float4*)(out + off + j4 * 4) =
            make_float4(acc[j4*4], acc[j4*4+1], acc[j4*4+2], acc[j4*4+3]);
}

// ---------------- launch ----------------------------------------------------
extern "C" void kernel_launch(void* const* d_in, const int* in_sizes, int n_in,
                              void* d_out, int out_size)
{
    (void)out_size;
    // expected order: x, context, w_q, w_kv, w_out, ln_g, ln_b
    int ix = 0, ictx = 1, iwq = 2, iwkv = 3, iwout = 4, ig = 5, ib = 6;
    int g_seen = -1;
    for (int i = 0; i < n_in; i++) {
        switch (in_sizes[i]) {
            case 7864320:  ix = i;    break;
            case 78643200: ictx = i;  break;
            case 65536:    iwq = i;   break;
            case 131072:   iwkv = i;  break;
            case 8192:     iwout = i; break;
            case 256:
                if (g_seen < 0) { ig = i; g_seen = i; } else { ib = i; }
                break;
            default: break;
        }
    }

    const float* x    = (const float*)d_in[ix];
    const float* ctx  = (const float*)d_in[ictx];
    const float* wq   = (const float*)d_in[iwq];
    const float* wkv  = (const float*)d_in[iwkv];
    const float* wout = (const float*)d_in[iwout];
    const float* lng  = (const float*)d_in[ig];
    const float* lnb  = (const float*)d_in[ib];
    float* out = (float*)d_out;

    wprep_kernel<<<NQKV, 256>>>(wq, wkv);
    ln_kernel<<<NROWS/8, 256>>>(x, lng, lnb);

    dim3 g2(6, 240);
    qkv_mma<<<g2, 256>>>();

    dim3 g3(5, HEADS, BATCH);
    attn_mma<<<g3, 128>>>(ctx);

    outproj_kernel<<<240, 128>>>(wout, out);
}